// round 4
// baseline (speedup 1.0000x reference)
#include <cuda_runtime.h>

#define EPS 1e-12f

__device__ __forceinline__ float micro_scale(
    float lx, float ly, float lz,
    float nx, float ny, float nz,
    float vx, float vy, float vz,
    float e)
{
    // half vector
    float hx = lx + vx, hy = ly + vy, hz = lz + vz;
    float hnorm = sqrtf(hx * hx + hy * hy + hz * hz);
    float inv = 1.0f / fmaxf(hnorm, EPS);
    hx *= inv; hy *= inv; hz *= inv;

    float nl = nx * lx + ny * ly + nz * lz;
    float nv = nx * vx + ny * vy + nz * vz;
    float vh = vx * hx + vy * hy + vz * hz;

    float d_term = 0.0f;
    float g_term = nl * nv;

    float c  = vh;
    float gg = e * e + c * c - 1.0f;
    float gs = sqrtf(fmaxf(gg, EPS));
    float a  = (gs - c) / (gs + c);
    float b  = (c * (gs + c) - 1.0f) / (c * (gs - c) + 1.0f);
    float fr = (gg > 0.0f) ? (0.5f * a * a * (1.0f + b * b)) : 1.0f;

    float denom = 4.0f * nl * nv;
    return d_term * g_term * fr / denom;
}

// Block of 256 threads processes 256 points through shared memory.
// Global traffic is pure float4; compute reads AoS from smem (conflict-free).
__global__ __launch_bounds__(256) void microfacet_smem(
    const float* __restrict__ in,
    const float* __restrict__ base_color,
    const float* __restrict__ eta_p,
    float* __restrict__ out,
    int n)
{
    __shared__ float sIn[256 * 9];   // 9216 B
    __shared__ float sOut[256 * 3];  // 3072 B

    const int tid  = threadIdx.x;
    const int base = blockIdx.x * 256;
    const int npts = min(256, n - base);

    // ---- stage in ----
    if (npts == 256) {
        // base*9 = blockIdx*2304 floats -> 16B aligned; 576 float4 total
        const float4* g4 = (const float4*)(in + (size_t)base * 9);
        float4* s4 = (float4*)sIn;
        s4[tid]       = g4[tid];
        s4[tid + 256] = g4[tid + 256];
        if (tid < 64) s4[tid + 512] = g4[tid + 512];
    } else {
        for (int j = tid; j < npts * 9; j += 256)
            sIn[j] = in[(size_t)base * 9 + j];
    }
    __syncthreads();

    // ---- compute ----
    const float e   = __ldg(eta_p);
    const float bc0 = __ldg(base_color + 0);
    const float bc1 = __ldg(base_color + 1);
    const float bc2 = __ldg(base_color + 2);

    if (tid < npts) {
        const float* p = sIn + tid * 9;
        float s = micro_scale(p[0], p[1], p[2],
                              p[3], p[4], p[5],
                              p[6], p[7], p[8], e);
        sOut[tid * 3 + 0] = bc0 * s;
        sOut[tid * 3 + 1] = bc1 * s;
        sOut[tid * 3 + 2] = bc2 * s;
    }
    __syncthreads();

    // ---- stage out ----
    if (npts == 256) {
        float4* g4o = (float4*)(out + (size_t)base * 3);  // 192 float4
        const float4* s4o = (const float4*)sOut;
        if (tid < 192) g4o[tid] = s4o[tid];
    } else {
        for (int j = tid; j < npts * 3; j += 256)
            out[(size_t)base * 3 + j] = sOut[j];
    }
}

extern "C" void kernel_launch(void* const* d_in, const int* in_sizes, int n_in,
                              void* d_out, int out_size)
{
    const float* in         = (const float*)d_in[0];
    const float* base_color = (const float*)d_in[1];
    // d_in[2] is alpha (unused by the reference math)
    const float* eta        = (const float*)d_in[3];
    float* out = (float*)d_out;

    int n = in_sizes[0] / 9;
    int blocks = (n + 255) / 256;
    microfacet_smem<<<blocks, 256>>>(in, base_color, eta, out, n);
}